// round 9
// baseline (speedup 1.0000x reference)
#include <cuda_runtime.h>
#include <math.h>

#define Bsz 64
#define Tn  12
#define Dd  256
#define Vv  512
#define Ss  512
#define BT  768
#define NB  128   // all CTAs co-resident (128 <= 148 SMs)
#define NGRP 8
#define GSZ  16   // 128/8

// scratch (no allocations allowed)
__device__ float g_gs[Bsz * 2 * Dd];                   // graph_state [64, 512]
__device__ __align__(16) float g_hp[8 * 2 * Bsz * Dd]; // hidden partials [ks][z][64][256]
__device__ float    g_stepGate[Bsz][Tn];               // step gate values (producer->consumer)
__device__ unsigned g_bars[NGRP * 16];                 // grouped barrier counters (64B stride)
__device__ unsigned g_pair[Bsz * 16];                  // per-batch 2-party sync (64B stride)

__device__ __forceinline__ float gelu_exact(float x) {
    return 0.5f * x * (1.0f + erff(x * 0.70710678118654752440f));
}
__device__ __forceinline__ float sigmoidf_(float x) {
    return 1.0f / (1.0f + expf(-x));
}

// grid-wide barrier: 8 group counters, monotone tickets, wrap-safe.
__device__ __forceinline__ void grid_sync(int bx) {
    __syncthreads();
    if (threadIdx.x == 0) {
        __threadfence();
        unsigned t = atomicAdd(&g_bars[(bx & (NGRP - 1)) * 16], 1u);
        unsigned target = (t / GSZ + 1u) * GSZ;
        #pragma unroll
        for (int j = 0; j < NGRP; j++)
            while ((int)(*(volatile unsigned*)&g_bars[j * 16] - target) < 0) { }
    }
    __syncthreads();
}

// 2-party sync between block pair sharing batch b. monotone, wrap-safe.
__device__ __forceinline__ void pair_sync(int b) {
    __syncthreads();
    if (threadIdx.x == 0) {
        __threadfence();
        unsigned t = atomicAdd(&g_pair[b * 16], 1u);
        unsigned target = (t / 2u + 1u) * 2u;
        while ((int)(*(volatile unsigned*)&g_pair[b * 16] - target) < 0) { }
    }
    __syncthreads();
}

// ---------------------------------------------------------------------------
__global__ void __launch_bounds__(256)
k_all(const int* __restrict__ marker, const int* __restrict__ srcI,
      const int* __restrict__ sv,
      const int* __restrict__ tsymI, const int* __restrict__ tsv,
      const int* __restrict__ tvalI, const int* __restrict__ tvv,
      const int* __restrict__ qI, const int* __restrict__ qV,
      const float* __restrict__ evidence,
      const float* __restrict__ symbol_emb, const float* __restrict__ value_emb,
      const float* __restrict__ Wmg1, const float* __restrict__ bmg1,
      const float* __restrict__ Wmg2, const float* __restrict__ bmg2,
      const float* __restrict__ Wsg1, const float* __restrict__ bsg1,
      const float* __restrict__ Wsg2, const float* __restrict__ bsg2,
      const float* __restrict__ Wf1,  const float* __restrict__ bf1,
      const float* __restrict__ Wf2,  const float* __restrict__ bf2,
      const float* __restrict__ Wo1,  const float* __restrict__ bo1,
      const float* __restrict__ Wo2,  const float* __restrict__ bo2,
      float* __restrict__ out)
{
    const int bx  = blockIdx.x;
    const int tid = threadIdx.x;
    const int lane = tid & 31, w = tid >> 5;

    __shared__ int   e_m[Tn], e_src[Tn], e_sv[Tn], e_ts[Tn], e_tsv[Tn], e_tv[Tn], e_tvv[Tn];
    __shared__ int   e_q, e_qv;
    __shared__ int   jobT[2][Tn];
    __shared__ int   nJob[2];
    __shared__ float gateV0[Tn];                        // map gates (consumer-local)
    __shared__ __align__(16) float s_ev[Tn][Dd];        // all evidence rows (12KB)
    __shared__ __align__(16) float s_part[4][4][Dd];    // [kq][job][col] (16KB)
    __shared__ float red[4][8];
    __shared__ float walk[2][Ss];
    __shared__ float wsum[Ss];
    __shared__ int   wsI[64]; __shared__ float wsW[64];
    __shared__ int   avI[16]; __shared__ float avW[16];
    __shared__ int   s_nws, s_nav;
    __shared__ int   mS[Tn], mT[Tn]; __shared__ float mW[Tn];
    __shared__ int   sS[Tn], sT[Tn]; __shared__ float sW[Tn];

    // ======================= PHASE 1: gates (pair-split) + walk ==============
    {
        const int b = bx & (Bsz - 1);
        const int g = bx >> 6;                 // 0: map (consumer), 1: step (producer)

        if (tid < Tn) {
            int idx = b * Tn + tid;
            e_m[tid]   = marker[idx];
            e_src[tid] = srcI[idx];
            e_sv[tid]  = sv[idx];
            e_ts[tid]  = tsymI[idx];
            e_tsv[tid] = tsv[idx];
            e_tv[tid]  = tvalI[idx];
            e_tvv[tid] = tvv[idx];
        }
        if (tid == Tn) { e_q = qI[b]; e_qv = qV[b]; }
        // stage all 12 evidence rows: 12 loads/thread, independent
        #pragma unroll
        for (int r = 0; r < Tn; r++)
            s_ev[r][tid] = evidence[(b * Tn + r) * Dd + tid];
        if (g == 0)
            for (int i = tid; i < Ss; i += 256) { walk[0][i] = 0.f; wsum[i] = 0.f; }
        __syncthreads();

        if (tid == 0) {
            int nm = 0, ns = 0;
            #pragma unroll
            for (int t = 0; t < Tn; t++) {
                int m = e_m[t];
                bool svv = e_sv[t] > 0;
                if (((m == 0) || (m == 1)) && svv && e_tvv[t] > 0) jobT[0][nm++] = t;
                if (m == 2 && svv && e_tsv[t] > 0)                 jobT[1][ns++] = t;
            }
            nJob[0] = nm; nJob[1] = ns;
        }
        __syncthreads();

        // gate MLP for this block's type only
        const float* W1 = g ? Wsg1 : Wmg1;
        const float* B1 = g ? bsg1 : bmg1;
        const float* W2 = g ? Wsg2 : Wmg2;
        const float  b2 = g ? bsg2[0] : bmg2[0];
        const int nj = nJob[g];

        const int cg = w & 1, kq = w >> 1;
        const int colb = cg * 128 + lane * 4;

        for (int j0 = 0; j0 < nj; j0 += 4) {
            int cnt = nj - j0; if (cnt > 4) cnt = 4;
            const int t0 = jobT[g][j0];
            const int t1 = jobT[g][j0 + (1 < cnt ? 1 : 0)];
            const int t2 = jobT[g][j0 + (2 < cnt ? 2 : 0)];
            const int t3 = jobT[g][j0 + (3 < cnt ? 3 : 0)];

            float4 a0 = {0,0,0,0}, a1 = {0,0,0,0}, a2 = {0,0,0,0}, a3 = {0,0,0,0};
            const float* Wp = W1 + (kq * 64) * Dd + colb;
            #pragma unroll 16
            for (int kk = 0; kk < 64; kk++) {
                float4 wv = *(const float4*)(Wp + kk * Dd);
                int k = kq * 64 + kk;
                float x0 = s_ev[t0][k], x1 = s_ev[t1][k], x2 = s_ev[t2][k], x3 = s_ev[t3][k];
                a0.x += x0*wv.x; a0.y += x0*wv.y; a0.z += x0*wv.z; a0.w += x0*wv.w;
                a1.x += x1*wv.x; a1.y += x1*wv.y; a1.z += x1*wv.z; a1.w += x1*wv.w;
                a2.x += x2*wv.x; a2.y += x2*wv.y; a2.z += x2*wv.z; a2.w += x2*wv.w;
                a3.x += x3*wv.x; a3.y += x3*wv.y; a3.z += x3*wv.z; a3.w += x3*wv.w;
            }
            *(float4*)&s_part[kq][0][colb] = a0;
            *(float4*)&s_part[kq][1][colb] = a1;
            *(float4*)&s_part[kq][2][colb] = a2;
            *(float4*)&s_part[kq][3][colb] = a3;
            __syncthreads();

            float b1v = B1[tid], w2v = W2[tid];
            float h0 = gelu_exact(s_part[0][0][tid] + s_part[1][0][tid] + s_part[2][0][tid] + s_part[3][0][tid] + b1v) * w2v;
            float h1 = gelu_exact(s_part[0][1][tid] + s_part[1][1][tid] + s_part[2][1][tid] + s_part[3][1][tid] + b1v) * w2v;
            float h2 = gelu_exact(s_part[0][2][tid] + s_part[1][2][tid] + s_part[2][2][tid] + s_part[3][2][tid] + b1v) * w2v;
            float h3 = gelu_exact(s_part[0][3][tid] + s_part[1][3][tid] + s_part[2][3][tid] + s_part[3][3][tid] + b1v) * w2v;
            #pragma unroll
            for (int off = 16; off > 0; off >>= 1) {
                h0 += __shfl_down_sync(0xffffffffu, h0, off);
                h1 += __shfl_down_sync(0xffffffffu, h1, off);
                h2 += __shfl_down_sync(0xffffffffu, h2, off);
                h3 += __shfl_down_sync(0xffffffffu, h3, off);
            }
            if (lane == 0) { red[0][w] = h0; red[1][w] = h1; red[2][w] = h2; red[3][w] = h3; }
            __syncthreads();
            if (tid < cnt) {
                float s = red[tid][0] + red[tid][1] + red[tid][2] + red[tid][3]
                        + red[tid][4] + red[tid][5] + red[tid][6] + red[tid][7];
                float gate = sigmoidf_(s + b2);
                if (g == 0) gateV0[j0 + tid] = gate;
                else        g_stepGate[b][j0 + tid] = gate;
            }
            __syncthreads();
        }

        pair_sync(b);   // producer releases step gates; consumer acquires

        if (g == 1) {
            // producer: bias-init this batch's output slice, then go to barrier
            #pragma unroll
            for (int j = tid; j < BT; j += 256) {
                int i = b * BT + j;
                out[i] = (i < Bsz * Vv) ? bo2[i & (Vv - 1)] : bf2[i & (Dd - 1)];
            }
        } else {
            // consumer: sparse edge lists + walk + gather
            if (tid == 0) {
                for (int q = 0; q < nJob[0]; q++) {
                    int t = jobT[0][q];
                    int src = e_src[t]; src = min(max(src, 0), Ss - 1);
                    int tv  = e_tv[t];  tv  = min(max(tv, 0), Vv - 1);
                    mS[q] = src; mT[q] = tv; mW[q] = gateV0[q];
                }
                for (int q = 0; q < nJob[1]; q++) {
                    int t = jobT[1][q];
                    int src = e_src[t]; src = min(max(src, 0), Ss - 1);
                    int ts  = e_ts[t];  ts  = min(max(ts, 0), Ss - 1);
                    sS[q] = src; sT[q] = ts; sW[q] = __ldcg(&g_stepGate[b][q]);
                }
                int q = e_q; q = min(max(q, 0), Ss - 1);
                float qv = (float)e_qv;
                walk[0][q] = qv;
                wsum[q]    = qv;
                wsI[0] = q; wsW[0] = qv;
                s_nws = 1;
            }
            __syncthreads();

            int cur = 0;
            for (int it = 0; it < 3; it++) {
                for (int i = tid; i < Ss; i += 256) walk[cur ^ 1][i] = 0.f;
                __syncthreads();
                if (tid == 0) {
                    int ns = nJob[1], nws = s_nws;
                    for (int e = 0; e < ns; e++) {
                        float v = walk[cur][sS[e]];
                        if (v != 0.f) {
                            float c = v * sW[e];
                            walk[cur ^ 1][sT[e]] += c;
                            wsum[sT[e]] += c;
                            wsI[nws] = sT[e]; wsW[nws] = c; nws++;
                        }
                    }
                    s_nws = nws;
                }
                __syncthreads();
                cur ^= 1;
            }

            if (tid == 0) {
                int na = 0;
                for (int e = 0; e < nJob[0]; e++) {
                    float v = wsum[mS[e]];
                    if (v != 0.f) { avI[na] = mT[e]; avW[na] = v * mW[e]; na++; }
                }
                s_nav = na;
            }
            __syncthreads();

            const int d = tid;
            const int nws = s_nws, nav = s_nav;
            float ss = 0.f;
            for (int p = 0; p < nws; p++) ss += wsW[p] * symbol_emb[wsI[p] * Dd + d];
            float vv = 0.f;
            for (int p = 0; p < nav; p++) vv += avW[p] * value_emb[avI[p] * Dd + d];
            g_gs[b * (2 * Dd) + d]      = ss;
            g_gs[b * (2 * Dd) + Dd + d] = vv;
        }
    }

    grid_sync(bx);

    // ======================= PHASE 2: hidden partials, split-K=8 =============
    // 128 tiles: x = zks*8 + rowt*2 + colt
    {
        const int colt = bx & 1, rowt = (bx >> 1) & 3, zks = bx >> 3;
        const int z = zks >> 3, ks = zks & 7;
        const float* W1 = z ? Wf1 : Wo1;
        const int rr = tid >> 5;

        float (*gsS)[64] = (float(*)[64])walk;  // reuse smem
        for (int i = tid; i < 1024; i += 256) {
            int r = i >> 6, kk = i & 63;
            gsS[r][kk] = __ldcg(&g_gs[(rowt * 16 + r) * 512 + ks * 64 + kk]);
        }
        __syncthreads();

        const int col = colt * 128 + lane * 4;
        const float* Wp = W1 + (ks * 64) * Dd + col;
        float4 a0 = {0,0,0,0}, a1 = {0,0,0,0};
        #pragma unroll 16
        for (int kk = 0; kk < 64; kk++) {
            float4 wv = *(const float4*)(Wp + kk * Dd);
            float x0 = gsS[rr][kk], x1 = gsS[rr + 8][kk];
            a0.x += x0*wv.x; a0.y += x0*wv.y; a0.z += x0*wv.z; a0.w += x0*wv.w;
            a1.x += x1*wv.x; a1.y += x1*wv.y; a1.z += x1*wv.z; a1.w += x1*wv.w;
        }
        const int base = ((ks * 2 + z) * Bsz) * Dd;
        const int r0 = rowt * 16 + rr;
        *(float4*)&g_hp[base + r0 * Dd + col]       = a0;
        *(float4*)&g_hp[base + (r0 + 8) * Dd + col] = a1;
    }

    grid_sync(bx);

    // ======================= PHASE 3: output, split-K=4 + atomics ============
    // x = z4*16 + rowt*4 + colt ; z4 = z*4+ks
    {
        const int colt = bx & 3, rowt = (bx >> 2) & 3, z4 = bx >> 4;
        const int z = z4 >> 2, ks = z4 & 3;
        const int OW = z ? Dd : Vv;
        if (colt * 128 < OW) {
            const float* W2 = z ? Wf2 : Wo2;
            const float* B1 = z ? bf1 : bo1;
            const int rr = tid >> 5;

            float (*hS)[64] = (float(*)[64])walk;  // reuse smem
            for (int i = tid; i < 1024; i += 256) {
                int r = i >> 6, kk = i & 63;
                int c = ks * 64 + kk;
                int row = rowt * 16 + r;
                float s = 0.f;
                #pragma unroll
                for (int ks2 = 0; ks2 < 8; ks2++)
                    s += __ldcg(&g_hp[((ks2 * 2 + z) * Bsz + row) * Dd + c]);
                hS[r][kk] = gelu_exact(s + B1[c]);
            }
            __syncthreads();

            const int col = colt * 128 + lane * 4;
            const float* Wp = W2 + (ks * 64) * OW + col;
            float4 a0 = {0,0,0,0}, a1 = {0,0,0,0};
            #pragma unroll 16
            for (int kk = 0; kk < 64; kk++) {
                float4 wv = *(const float4*)(Wp + kk * OW);
                float x0 = hS[rr][kk], x1 = hS[rr + 8][kk];
                a0.x += x0*wv.x; a0.y += x0*wv.y; a0.z += x0*wv.z; a0.w += x0*wv.w;
                a1.x += x1*wv.x; a1.y += x1*wv.y; a1.z += x1*wv.z; a1.w += x1*wv.w;
            }
            float* ob = z ? (out + Bsz * Vv) : out;
            const int r0 = rowt * 16 + rr;
            float* p0 = ob + r0 * OW + col;
            float* p1 = ob + (r0 + 8) * OW + col;
            atomicAdd(p0 + 0, a0.x); atomicAdd(p0 + 1, a0.y);
            atomicAdd(p0 + 2, a0.z); atomicAdd(p0 + 3, a0.w);
            atomicAdd(p1 + 0, a1.x); atomicAdd(p1 + 1, a1.y);
            atomicAdd(p1 + 2, a1.z); atomicAdd(p1 + 3, a1.w);
        }
    }
}

// ---------------------------------------------------------------------------
extern "C" void kernel_launch(void* const* d_in, const int* in_sizes, int n_in,
                              void* d_out, int out_size)
{
    const int*   marker     = (const int*)d_in[0];
    const int*   srcI       = (const int*)d_in[1];
    const int*   sv         = (const int*)d_in[2];
    const int*   tsymI      = (const int*)d_in[3];
    const int*   tsv        = (const int*)d_in[4];
    const int*   tvalI      = (const int*)d_in[5];
    const int*   tvv        = (const int*)d_in[6];
    const int*   qI         = (const int*)d_in[7];
    const int*   qV         = (const int*)d_in[8];
    const float* evidence   = (const float*)d_in[9];
    const float* symbol_emb = (const float*)d_in[10];
    const float* value_emb  = (const float*)d_in[11];
    const float* Wmg1 = (const float*)d_in[12]; const float* bmg1 = (const float*)d_in[13];
    const float* Wmg2 = (const float*)d_in[14]; const float* bmg2 = (const float*)d_in[15];
    const float* Wsg1 = (const float*)d_in[16]; const float* bsg1 = (const float*)d_in[17];
    const float* Wsg2 = (const float*)d_in[18]; const float* bsg2 = (const float*)d_in[19];
    const float* Wf1  = (const float*)d_in[20]; const float* bf1  = (const float*)d_in[21];
    const float* Wf2  = (const float*)d_in[22]; const float* bf2  = (const float*)d_in[23];
    const float* Wo1  = (const float*)d_in[24]; const float* bo1  = (const float*)d_in[25];
    const float* Wo2  = (const float*)d_in[26]; const float* bo2  = (const float*)d_in[27];
    float* out = (float*)d_out;

    k_all<<<NB, 256>>>(marker, srcI, sv, tsymI, tsv, tvalI, tvv, qI, qV,
                       evidence, symbol_emb, value_emb,
                       Wmg1, bmg1, Wmg2, bmg2, Wsg1, bsg1, Wsg2, bsg2,
                       Wf1, bf1, Wf2, bf2, Wo1, bo1, Wo2, bo2, out);
}

// round 10
// speedup vs baseline: 1.2766x; 1.2766x over previous
#include <cuda_runtime.h>
#include <math.h>

#define Bsz 64
#define Tn  12
#define Dd  256
#define Vv  512
#define Ss  512
#define NB  128   // all CTAs co-resident in one wave (128 <= 148 SMs)

// ---- persistent scratch (no allocations allowed) ----
__device__ unsigned g_launch = 0;                 // launch epoch ticket
__device__ unsigned g_gsF[Bsz * 16];              // gs ready flags   (64B stride)
__device__ unsigned g_sgF[Bsz * 16];              // step-gate flags  (64B stride)
__device__ unsigned g_hF[32 * 16];                // h tile flags [z*16+rowt]
__device__ float    g_gs[Bsz * 2 * Dd];           // graph_state [64][512]
__device__ float    g_stepGate[Bsz][Tn];          // step gates (producer->consumer)
__device__ __align__(16) float g_h[2 * Bsz * Dd]; // gelu'd hidden [z][64][256]

__device__ __forceinline__ float gelu_exact(float x) {
    return 0.5f * x * (1.0f + erff(x * 0.70710678118654752440f));
}
__device__ __forceinline__ float sigmoidf_(float x) {
    return 1.0f / (1.0f + expf(-x));
}
__device__ __forceinline__ unsigned ldvol(const unsigned* p) {
    return *(volatile const unsigned*)p;
}

// ---------------------------------------------------------------------------
__global__ void __launch_bounds__(256)
k_all(const int* __restrict__ marker, const int* __restrict__ srcI,
      const int* __restrict__ sv,
      const int* __restrict__ tsymI, const int* __restrict__ tsv,
      const int* __restrict__ tvalI, const int* __restrict__ tvv,
      const int* __restrict__ qI, const int* __restrict__ qV,
      const float* __restrict__ evidence,
      const float* __restrict__ symbol_emb, const float* __restrict__ value_emb,
      const float* __restrict__ Wmg1, const float* __restrict__ bmg1,
      const float* __restrict__ Wmg2, const float* __restrict__ bmg2,
      const float* __restrict__ Wsg1, const float* __restrict__ bsg1,
      const float* __restrict__ Wsg2, const float* __restrict__ bsg2,
      const float* __restrict__ Wf1,  const float* __restrict__ bf1,
      const float* __restrict__ Wf2,  const float* __restrict__ bf2,
      const float* __restrict__ Wo1,  const float* __restrict__ bo1,
      const float* __restrict__ Wo2,  const float* __restrict__ bo2,
      float* __restrict__ out)
{
    const int bx  = blockIdx.x;
    const int tid = threadIdx.x;
    const int lane = tid & 31, w = tid >> 5;

    __shared__ __align__(16) float pool[7168];     // 28KB, reused per phase
    __shared__ int   e_src[Tn], e_ts[Tn], e_tv[Tn];
    __shared__ int   jobT[2][Tn];
    __shared__ int   nJob[2];
    __shared__ float gateV0[Tn];
    __shared__ float red[4][8];
    __shared__ int   wsI[40]; __shared__ float wsW[40];   // 1+3*12 = 37 used
    __shared__ int   avI[Tn]; __shared__ float avW[Tn];
    __shared__ unsigned s_L;
    __shared__ int   s_q; __shared__ float s_qv;

    if (tid == 0) s_L = atomicAdd(&g_launch, 1u) / NB;   // launch epoch

    // ======================= PHASE 1: gates (pair-split) + walk ==============
    const int b = bx & (Bsz - 1);
    const int g = bx >> 6;                 // 0: map gates + walk, 1: step gates

    // warp 0: load events, clamp, build job lists via ballot
    if (w == 0) {
        int fm = 0, fs = 0;
        if (lane < Tn) {
            int idx = b * Tn + lane;
            int m    = marker[idx];
            int svv  = sv[idx];
            int tsvv = tsv[idx];
            int tvvv = tvv[idx];
            e_src[lane] = min(max(srcI[idx],  0), Ss - 1);
            e_ts[lane]  = min(max(tsymI[idx], 0), Ss - 1);
            e_tv[lane]  = min(max(tvalI[idx], 0), Vv - 1);
            fm = (((m == 0) || (m == 1)) && svv > 0 && tvvv > 0) ? 1 : 0;
            fs = ((m == 2) && svv > 0 && tsvv > 0) ? 1 : 0;
        }
        unsigned bm = __ballot_sync(0xffffffffu, fm);
        unsigned bs = __ballot_sync(0xffffffffu, fs);
        if (fm) jobT[0][__popc(bm & ((1u << lane) - 1u))] = lane;
        if (fs) jobT[1][__popc(bs & ((1u << lane) - 1u))] = lane;
        if (lane == 0) { nJob[0] = __popc(bm); nJob[1] = __popc(bs); }
        if (lane == Tn) { s_q = min(max(qI[b], 0), Ss - 1); s_qv = (float)qV[b]; }
    }
    __syncthreads();

    const unsigned Lt = s_L + 1u;          // per-launch flag target
    const int nj = nJob[g];

    // stage only the active jobs' evidence rows
    float* s_ev   = pool;                  // [<=12][256]
    float* s_part = pool + Tn * Dd;        // [4][4][256]
    for (int jj = 0; jj < nj; jj++)
        s_ev[jj * Dd + tid] = evidence[(b * Tn + jobT[g][jj]) * Dd + tid];
    __syncthreads();

    // gate MLP passes (4 jobs max per pass; fast path for <=2)
    {
        const float* W1 = g ? Wsg1 : Wmg1;
        const float* B1 = g ? bsg1 : bmg1;
        const float* W2 = g ? Wsg2 : Wmg2;
        const float  b2 = g ? bsg2[0] : bmg2[0];
        const int cg = w & 1, kq = w >> 1;
        const int colb = cg * 128 + lane * 4;

        for (int j0 = 0; j0 < nj; j0 += 4) {
            int cnt = nj - j0; if (cnt > 4) cnt = 4;
            const float* Wp = W1 + (kq * 64) * Dd + colb;
            const float* x0 = s_ev + (j0) * Dd;
            const float* x1 = s_ev + (j0 + (cnt > 1 ? 1 : 0)) * Dd;

            if (cnt <= 2) {
                float4 a0 = {0,0,0,0}, a1 = {0,0,0,0};
                #pragma unroll 16
                for (int kk = 0; kk < 64; kk++) {
                    float4 wv = *(const float4*)(Wp + kk * Dd);
                    int k = kq * 64 + kk;
                    float v0 = x0[k], v1 = x1[k];
                    a0.x += v0*wv.x; a0.y += v0*wv.y; a0.z += v0*wv.z; a0.w += v0*wv.w;
                    a1.x += v1*wv.x; a1.y += v1*wv.y; a1.z += v1*wv.z; a1.w += v1*wv.w;
                }
                *(float4*)&s_part[(kq * 4 + 0) * Dd + colb] = a0;
                *(float4*)&s_part[(kq * 4 + 1) * Dd + colb] = a1;
            } else {
                const float* x2 = s_ev + (j0 + 2) * Dd;
                const float* x3 = s_ev + (j0 + (cnt > 3 ? 3 : 2)) * Dd;
                float4 a0 = {0,0,0,0}, a1 = {0,0,0,0}, a2 = {0,0,0,0}, a3 = {0,0,0,0};
                #pragma unroll 16
                for (int kk = 0; kk < 64; kk++) {
                    float4 wv = *(const float4*)(Wp + kk * Dd);
                    int k = kq * 64 + kk;
                    float v0 = x0[k], v1 = x1[k], v2 = x2[k], v3 = x3[k];
                    a0.x += v0*wv.x; a0.y += v0*wv.y; a0.z += v0*wv.z; a0.w += v0*wv.w;
                    a1.x += v1*wv.x; a1.y += v1*wv.y; a1.z += v1*wv.z; a1.w += v1*wv.w;
                    a2.x += v2*wv.x; a2.y += v2*wv.y; a2.z += v2*wv.z; a2.w += v2*wv.w;
                    a3.x += v3*wv.x; a3.y += v3*wv.y; a3.z += v3*wv.z; a3.w += v3*wv.w;
                }
                *(float4*)&s_part[(kq * 4 + 0) * Dd + colb] = a0;
                *(float4*)&s_part[(kq * 4 + 1) * Dd + colb] = a1;
                *(float4*)&s_part[(kq * 4 + 2) * Dd + colb] = a2;
                *(float4*)&s_part[(kq * 4 + 3) * Dd + colb] = a3;
            }
            __syncthreads();

            float b1v = B1[tid], w2v = W2[tid];
            for (int q = 0; q < cnt; q++) {
                float h = gelu_exact(s_part[(0 * 4 + q) * Dd + tid] + s_part[(1 * 4 + q) * Dd + tid]
                                   + s_part[(2 * 4 + q) * Dd + tid] + s_part[(3 * 4 + q) * Dd + tid]
                                   + b1v) * w2v;
                #pragma unroll
                for (int off = 16; off > 0; off >>= 1)
                    h += __shfl_down_sync(0xffffffffu, h, off);
                if (lane == 0) red[q][w] = h;
            }
            __syncthreads();
            if (tid < cnt) {
                float s = red[tid][0] + red[tid][1] + red[tid][2] + red[tid][3]
                        + red[tid][4] + red[tid][5] + red[tid][6] + red[tid][7];
                float gate = sigmoidf_(s + b2);
                if (g == 0) gateV0[j0 + tid] = gate;
                else { g_stepGate[b][j0 + tid] = gate; __threadfence(); }
            }
            __syncthreads();
        }
    }

    if (g == 1) {
        if (tid == 0) atomicAdd(&g_sgF[b * 16], 1u);   // release step gates
    } else {
        // wait for step gates
        if (tid == 0)
            while ((int)(ldvol(&g_sgF[b * 16]) - Lt) < 0) { }
        __syncthreads();

        const int nm = nJob[0], ns = nJob[1];

        // warp-collective sparse walk (<=12 step edges, 3 iterations)
        if (w == 0) {
            // init padded gather lists
            wsI[lane] = 0; wsW[lane] = 0.f;
            if (lane < 8) { wsI[32 + lane] = 0; wsW[32 + lane] = 0.f; }
            if (lane < Tn) { avI[lane] = 0; avW[lane] = 0.f; }

            int srcE = 0, tgtE = 0; float wE = 0.f;
            if (lane < ns) {
                int t = jobT[1][lane];
                srcE = e_src[t]; tgtE = e_ts[t];
                wE = __ldcg(&g_stepGate[b][lane]);
            }
            const int q = s_q; const float qv = s_qv;

            float c1 = (lane < ns && srcE == q) ? wE * qv : 0.f;
            float c2 = 0.f;
            for (int e = 0; e < ns; e++) {
                float ce = __shfl_sync(0xffffffffu, c1, e);
                int   te = __shfl_sync(0xffffffffu, tgtE, e);
                if (te == srcE) c2 += ce;
            }
            c2 *= wE;
            float c3 = 0.f;
            for (int e = 0; e < ns; e++) {
                float ce = __shfl_sync(0xffffffffu, c2, e);
                int   te = __shfl_sync(0xffffffffu, tgtE, e);
                if (te == srcE) c3 += ce;
            }
            c3 *= wE;
            float c123 = c1 + c2 + c3;

            // map readout weights: wm = mg * wsum[mSrc]
            int mSrc = 0, mTgt = 0; float mWt = 0.f;
            if (lane < nm) {
                int t = jobT[0][lane];
                mSrc = e_src[t]; mTgt = e_tv[t]; mWt = gateV0[lane];
            }
            float acc = (mSrc == q) ? qv : 0.f;
            for (int e = 0; e < ns; e++) {
                float ce = __shfl_sync(0xffffffffu, c123, e);
                int   te = __shfl_sync(0xffffffffu, tgtE, e);
                if (te == mSrc) acc += ce;
            }
            float wm = mWt * acc;

            __syncwarp();
            if (lane == 0) { wsI[0] = q; wsW[0] = qv; }
            if (lane < ns) {
                wsI[1 + lane]          = tgtE; wsW[1 + lane]          = c1;
                wsI[1 + ns + lane]     = tgtE; wsW[1 + ns + lane]     = c2;
                wsI[1 + 2 * ns + lane] = tgtE; wsW[1 + 2 * ns + lane] = c3;
            }
            if (lane < nm) { avI[lane] = mTgt; avW[lane] = wm; }
        }
        __syncthreads();

        // gather graph_state (fixed unrolled, zero-padded lists)
        float ss = 0.f, vv = 0.f;
        #pragma unroll
        for (int p = 0; p < 37; p++)
            ss += wsW[p] * __ldg(&symbol_emb[wsI[p] * Dd + tid]);
        #pragma unroll
        for (int p = 0; p < Tn; p++)
            vv += avW[p] * __ldg(&value_emb[avI[p] * Dd + tid]);
        g_gs[b * (2 * Dd) + tid]      = ss;
        g_gs[b * (2 * Dd) + Dd + tid] = vv;
        __threadfence();
        __syncthreads();
        if (tid == 0) atomicAdd(&g_gsF[b * 16], 1u);   // release gs[b]
    }

    // ======================= PHASE 2: hidden (full K=512) ====================
    // tile = bx: colt(4 x 64 cols) x rowt(16 x 4 rows) x z(2)
    {
        const int colt = bx & 3, rowt = (bx >> 2) & 15, z = bx >> 6;
        const float* W1 = z ? Wf1 : Wo1;
        const float* B1 = z ? bf1 : bo1;

        if (tid == 0) {
            const int b0 = rowt * 4;
            for (;;) {
                unsigned f0 = ldvol(&g_gsF[(b0 + 0) * 16]);
                unsigned f1 = ldvol(&g_gsF[(b0 + 1) * 16]);
                unsigned f2 = ldvol(&g_gsF[(b0 + 2) * 16]);
                unsigned f3 = ldvol(&g_gsF[(b0 + 3) * 16]);
                if ((int)(f0 - Lt) >= 0 && (int)(f1 - Lt) >= 0 &&
                    (int)(f2 - Lt) >= 0 && (int)(f3 - Lt) >= 0) break;
            }
        }
        __syncthreads();

        float* gs_s  = pool;           // [4][512]
        float* s_red = pool + 2048;    // [16][4][64]
        {
            const float4* src = (const float4*)&g_gs[rowt * 4 * 512];
            float4* dst = (float4*)gs_s;
            dst[tid]       = __ldcg(src + tid);
            dst[tid + 256] = __ldcg(src + tid + 256);
        }
        __syncthreads();

        const int cg = tid & 15, kq = tid >> 4;       // 16 col-groups x 16 k-chunks
        const int colg = colt * 64 + cg * 4;
        const float* Wp = W1 + (kq * 32) * Dd + colg;
        float4 a0 = {0,0,0,0}, a1 = {0,0,0,0}, a2 = {0,0,0,0}, a3 = {0,0,0,0};
        #pragma unroll
        for (int kk = 0; kk < 32; kk++) {
            float4 wv = *(const float4*)(Wp + kk * Dd);
            int k = kq * 32 + kk;
            float v0 = gs_s[k], v1 = gs_s[512 + k], v2 = gs_s[1024 + k], v3 = gs_s[1536 + k];
            a0.x += v0*wv.x; a0.y += v0*wv.y; a0.z += v0*wv.z; a0.w += v0*wv.w;
            a1.x += v1*wv.x; a1.y += v1*wv.y; a1.z += v1*wv.z; a1.w += v1*wv.w;
            a2.x += v2*wv.x; a2.y += v2*wv.y; a2.z += v2*wv.z; a2.w += v2*wv.w;
            a3.x += v3*wv.x; a3.y += v3*wv.y; a3.z += v3*wv.z; a3.w += v3*wv.w;
        }
        *(float4*)&s_red[(kq * 4 + 0) * 64 + cg * 4] = a0;
        *(float4*)&s_red[(kq * 4 + 1) * 64 + cg * 4] = a1;
        *(float4*)&s_red[(kq * 4 + 2) * 64 + cg * 4] = a2;
        *(float4*)&s_red[(kq * 4 + 3) * 64 + cg * 4] = a3;
        __syncthreads();

        {   // reduce 16 k-chunks -> 256 outputs (1/thread), gelu, store h
            int r = tid >> 6, c = tid & 63;
            float s = 0.f;
            #pragma unroll
            for (int k2 = 0; k2 < 16; k2++) s += s_red[(k2 * 4 + r) * 64 + c];
            float hv = gelu_exact(s + B1[colt * 64 + c]);
            g_h[(z * Bsz + rowt * 4 + r) * Dd + colt * 64 + c] = hv;
            __threadfence();
        }
        __syncthreads();
        if (tid == 0) atomicAdd(&g_hF[(z * 16 + rowt) * 16], 1u);
    }

    // ======================= PHASE 3: output (full K=256, direct store) ======
    if (bx < 96) {
        int z, rowt, colt;
        if (bx < 64) { z = 0; rowt = bx >> 2;        colt = bx & 3; }
        else         { z = 1; rowt = (bx - 64) >> 1; colt = (bx - 64) & 1; }
        const int OW = z ? Dd : Vv;
        const float* W2 = z ? Wf2 : Wo2;
        const float* B2 = z ? bf2 : bo2;

        if (tid == 0) {
            const unsigned tgt = 4u * Lt;
            while ((int)(ldvol(&g_hF[(z * 16 + rowt) * 16]) - tgt) < 0) { }
        }
        __syncthreads();

        float* h_s   = pool;          // [4][256]
        float* s_red = pool + 1024;   // [8][4][128]
        ((float4*)h_s)[tid] = __ldcg((const float4*)&g_h[(z * Bsz + rowt * 4) * Dd] + tid);
        __syncthreads();

        const int cg = tid & 31, kq = tid >> 5;      // 32 col-groups x 8 k-chunks
        const int colg = colt * 128 + cg * 4;
        const float* Wp = W2 + (kq * 32) * OW + colg;
        float4 a0 = {0,0,0,0}, a1 = {0,0,0,0}, a2 = {0,0,0,0}, a3 = {0,0,0,0};
        #pragma unroll
        for (int kk = 0; kk < 32; kk++) {
            float4 wv = *(const float4*)(Wp + kk * OW);
            int k = kq * 32 + kk;
            float v0 = h_s[k], v1 = h_s[256 + k], v2 = h_s[512 + k], v3 = h_s[768 + k];
            a0.x += v0*wv.x; a0.y += v0*wv.y; a0.z += v0*wv.z; a0.w += v0*wv.w;
            a1.x += v1*wv.x; a1.y += v1*wv.y; a1.z += v1*wv.z; a1.w += v1*wv.w;
            a2.x += v2*wv.x; a2.y += v2*wv.y; a2.z += v2*wv.z; a2.w += v2*wv.w;
            a3.x += v3*wv.x; a3.y += v3*wv.y; a3.z += v3*wv.z; a3.w += v3*wv.w;
        }
        *(float4*)&s_red[(kq * 4 + 0) * 128 + cg * 4] = a0;
        *(float4*)&s_red[(kq * 4 + 1) * 128 + cg * 4] = a1;
        *(float4*)&s_red[(kq * 4 + 2) * 128 + cg * 4] = a2;
        *(float4*)&s_red[(kq * 4 + 3) * 128 + cg * 4] = a3;
        __syncthreads();

        float* ob = z ? (out + Bsz * Vv) : out;
        #pragma unroll
        for (int u = 0; u < 2; u++) {
            int idx = tid + u * 256;
            int r = idx >> 7, c = idx & 127;
            float s = 0.f;
            #pragma unroll
            for (int k2 = 0; k2 < 8; k2++) s += s_red[(k2 * 4 + r) * 128 + c];
            ob[(rowt * 4 + r) * OW + colt * 128 + c] = s + B2[colt * 128 + c];
        }
    }
}

// ---------------------------------------------------------------------------
extern "C" void kernel_launch(void* const* d_in, const int* in_sizes, int n_in,
                              void* d_out, int out_size)
{
    const int*   marker     = (const int*)d_in[0];
    const int*   srcI       = (const int*)d_in[1];
    const int*   sv         = (const int*)d_in[2];
    const int*   tsymI      = (const int*)d_in[3];
    const int*   tsv        = (const int*)d_in[4];
    const int*   tvalI      = (const int*)d_in[5];
    const int*   tvv        = (const int*)d_in[6];
    const int*   qI         = (const int*)d_in[7];
    const int*   qV         = (const int*)d_in[8];
    const float* evidence   = (const float*)d_in[9];
    const float* symbol_emb = (const float*)d_in[10];
    const float* value_emb  = (const float*)d_in[11];
    const float* Wmg1 = (const float*)d_in[12]; const float* bmg1 = (const float*)d_in[13];
    const float* Wmg2 = (const float*)d_in[14]; const float* bmg2 = (const float*)d_in[15];
    const float* Wsg1 = (const float*)d_in[16]; const float* bsg1 = (const float*)d_in[17];
    const float* Wsg2 = (const float*)d_in[18]; const float* bsg2 = (const float*)d_in[19];
    const float* Wf1  = (const float*)d_in[20]; const float* bf1  = (const float*)d_in[21];
    const float* Wf2  = (const float*)d_in[22]; const float* bf2  = (const float*)d_in[23];
    const float* Wo1  = (const float*)d_in[24]; const float* bo1  = (const float*)d_in[25];
    const float* Wo2  = (const float*)d_in[26]; const float* bo2  = (const float*)d_in[27];
    float* out = (float*)d_out;

    k_all<<<NB, 256>>>(marker, srcI, sv, tsymI, tsv, tvalI, tvv, qI, qV,
                       evidence, symbol_emb, value_emb,
                       Wmg1, bmg1, Wmg2, bmg2, Wsg1, bsg1, Wsg2, bsg2,
                       Wf1, bf1, Wf2, bf2, Wo1, bo1, Wo2, bo2, out);
}

// round 11
// speedup vs baseline: 1.2799x; 1.0026x over previous
#include <cuda_runtime.h>
#include <math.h>

#define Bsz 64
#define Tn  12
#define Dd  256
#define Vv  512
#define Ss  512
#define NB  128   // all CTAs co-resident in one wave (128 <= 148 SMs)

// ---- persistent scratch (no allocations allowed) ----
__device__ unsigned g_ep[NB * 16];                // per-block launch counters (64B stride)
__device__ unsigned g_gsF[Bsz * 16];              // gs ready flags   (64B stride)
__device__ unsigned g_mgF[Bsz * 16];              // map-gate flags   (64B stride)
__device__ unsigned g_hF[32 * 16];                // h tile flags [z*16+rowt]
__device__ float    g_gs[Bsz * 2 * Dd];           // graph_state [64][512]
__device__ float    g_mg[Bsz][Tn];                // map gates (producer->walker)
__device__ __align__(16) float g_h[2 * Bsz * Dd]; // gelu'd hidden [z][64][256]

__device__ __forceinline__ float gelu_exact(float x) {
    return 0.5f * x * (1.0f + erff(x * 0.70710678118654752440f));
}
__device__ __forceinline__ float sigmoidf_(float x) {
    return 1.0f / (1.0f + expf(-x));
}
__device__ __forceinline__ unsigned ldvol(const unsigned* p) {
    return *(volatile const unsigned*)p;
}

// ---------------------------------------------------------------------------
__global__ void __launch_bounds__(256)
k_all(const int* __restrict__ marker, const int* __restrict__ srcI,
      const int* __restrict__ sv,
      const int* __restrict__ tsymI, const int* __restrict__ tsv,
      const int* __restrict__ tvalI, const int* __restrict__ tvv,
      const int* __restrict__ qI, const int* __restrict__ qV,
      const float* __restrict__ evidence,
      const float* __restrict__ symbol_emb, const float* __restrict__ value_emb,
      const float* __restrict__ Wmg1, const float* __restrict__ bmg1,
      const float* __restrict__ Wmg2, const float* __restrict__ bmg2,
      const float* __restrict__ Wsg1, const float* __restrict__ bsg1,
      const float* __restrict__ Wsg2, const float* __restrict__ bsg2,
      const float* __restrict__ Wf1,  const float* __restrict__ bf1,
      const float* __restrict__ Wf2,  const float* __restrict__ bf2,
      const float* __restrict__ Wo1,  const float* __restrict__ bo1,
      const float* __restrict__ Wo2,  const float* __restrict__ bo2,
      float* __restrict__ out)
{
    const int bx  = blockIdx.x;
    const int tid = threadIdx.x;
    const int lane = tid & 31, w = tid >> 5;

    __shared__ __align__(16) float pool[7168];     // 28KB, reused per phase
    __shared__ int   e_m[Tn], e_src[Tn], e_sv[Tn], e_ts[Tn], e_tsv[Tn], e_tv[Tn], e_tvv[Tn];
    __shared__ int   jobT[2][Tn];
    __shared__ int   nJob[2];
    __shared__ float gateL[Tn];                    // locally computed gates
    __shared__ float red[4][8];
    __shared__ int   wsI[40]; __shared__ float wsW[40];   // 1+3*12 = 37 used
    __shared__ int   avI[Tn]; __shared__ float avW[Tn];
    __shared__ unsigned s_L;
    __shared__ int   s_q; __shared__ float s_qv;

    // per-block private launch counter: zero contention, graph-replay safe
    if (tid == 0) {
        unsigned v = ldvol(&g_ep[bx * 16]);
        *(volatile unsigned*)&g_ep[bx * 16] = v + 1u;
        s_L = v;
    }

    // ======================= PHASE 1 =========================================
    // g=0: step gates (local) + walk + gather.  g=1: map gates -> global.
    const int b = bx & (Bsz - 1);
    const int g = bx >> 6;
    const int gt = 1 - g;                  // gate type computed here: 0=map, 1=step

    // parallel event load: 84 threads, one LDG each
    if (tid < 84) {
        const int a = tid / 12, t = tid - a * 12;
        const int idx = b * Tn + t;
        int v;
        switch (a) {
            case 0: e_m[t]   = marker[idx]; break;
            case 1: v = srcI[idx];  e_src[t] = min(max(v, 0), Ss - 1); break;
            case 2: e_sv[t]  = sv[idx]; break;
            case 3: v = tsymI[idx]; e_ts[t]  = min(max(v, 0), Ss - 1); break;
            case 4: e_tsv[t] = tsv[idx]; break;
            case 5: v = tvalI[idx]; e_tv[t]  = min(max(v, 0), Vv - 1); break;
            case 6: e_tvv[t] = tvv[idx]; break;
        }
    } else if (tid == 84) {
        s_q = min(max(qI[b], 0), Ss - 1); s_qv = (float)qV[b];
    }
    __syncthreads();

    if (w == 0) {
        int fm = 0, fs = 0;
        if (lane < Tn) {
            int m = e_m[lane];
            fm = (((m == 0) || (m == 1)) && e_sv[lane] > 0 && e_tvv[lane] > 0) ? 1 : 0;
            fs = ((m == 2) && e_sv[lane] > 0 && e_tsv[lane] > 0) ? 1 : 0;
        }
        unsigned bm = __ballot_sync(0xffffffffu, fm);
        unsigned bs = __ballot_sync(0xffffffffu, fs);
        if (fm) jobT[0][__popc(bm & ((1u << lane) - 1u))] = lane;
        if (fs) jobT[1][__popc(bs & ((1u << lane) - 1u))] = lane;
        if (lane == 0) { nJob[0] = __popc(bm); nJob[1] = __popc(bs); }
    }
    __syncthreads();

    const unsigned Lt = s_L + 1u;
    const int nj = nJob[gt];

    // stage active jobs' evidence rows
    float* s_ev   = pool;                  // [<=12][256]
    float* s_part = pool + Tn * Dd;        // [4][4][256]
    for (int jj = 0; jj < nj; jj++)
        s_ev[jj * Dd + tid] = evidence[(b * Tn + jobT[gt][jj]) * Dd + tid];
    __syncthreads();

    // gate MLP passes for this block's gate type
    {
        const float* W1 = gt ? Wsg1 : Wmg1;
        const float* B1 = gt ? bsg1 : bmg1;
        const float* W2 = gt ? Wsg2 : Wmg2;
        const float  b2 = gt ? bsg2[0] : bmg2[0];
        const int cg = w & 1, kq = w >> 1;
        const int colb = cg * 128 + lane * 4;

        for (int j0 = 0; j0 < nj; j0 += 4) {
            int cnt = nj - j0; if (cnt > 4) cnt = 4;
            const float* Wp = W1 + (kq * 64) * Dd + colb;
            const float* x0 = s_ev + (j0) * Dd;
            const float* x1 = s_ev + (j0 + (cnt > 1 ? 1 : 0)) * Dd;

            if (cnt <= 2) {
                float4 a0 = {0,0,0,0}, a1 = {0,0,0,0};
                #pragma unroll 16
                for (int kk = 0; kk < 64; kk++) {
                    float4 wv = *(const float4*)(Wp + kk * Dd);
                    int k = kq * 64 + kk;
                    float v0 = x0[k], v1 = x1[k];
                    a0.x += v0*wv.x; a0.y += v0*wv.y; a0.z += v0*wv.z; a0.w += v0*wv.w;
                    a1.x += v1*wv.x; a1.y += v1*wv.y; a1.z += v1*wv.z; a1.w += v1*wv.w;
                }
                *(float4*)&s_part[(kq * 4 + 0) * Dd + colb] = a0;
                *(float4*)&s_part[(kq * 4 + 1) * Dd + colb] = a1;
            } else {
                const float* x2 = s_ev + (j0 + 2) * Dd;
                const float* x3 = s_ev + (j0 + (cnt > 3 ? 3 : 2)) * Dd;
                float4 a0 = {0,0,0,0}, a1 = {0,0,0,0}, a2 = {0,0,0,0}, a3 = {0,0,0,0};
                #pragma unroll 16
                for (int kk = 0; kk < 64; kk++) {
                    float4 wv = *(const float4*)(Wp + kk * Dd);
                    int k = kq * 64 + kk;
                    float v0 = x0[k], v1 = x1[k], v2 = x2[k], v3 = x3[k];
                    a0.x += v0*wv.x; a0.y += v0*wv.y; a0.z += v0*wv.z; a0.w += v0*wv.w;
                    a1.x += v1*wv.x; a1.y += v1*wv.y; a1.z += v1*wv.z; a1.w += v1*wv.w;
                    a2.x += v2*wv.x; a2.y += v2*wv.y; a2.z += v2*wv.z; a2.w += v2*wv.w;
                    a3.x += v3*wv.x; a3.y += v3*wv.y; a3.z += v3*wv.z; a3.w += v3*wv.w;
                }
                *(float4*)&s_part[(kq * 4 + 0) * Dd + colb] = a0;
                *(float4*)&s_part[(kq * 4 + 1) * Dd + colb] = a1;
                *(float4*)&s_part[(kq * 4 + 2) * Dd + colb] = a2;
                *(float4*)&s_part[(kq * 4 + 3) * Dd + colb] = a3;
            }
            __syncthreads();

            float b1v = B1[tid], w2v = W2[tid];
            for (int q = 0; q < cnt; q++) {
                float h = gelu_exact(s_part[(0 * 4 + q) * Dd + tid] + s_part[(1 * 4 + q) * Dd + tid]
                                   + s_part[(2 * 4 + q) * Dd + tid] + s_part[(3 * 4 + q) * Dd + tid]
                                   + b1v) * w2v;
                #pragma unroll
                for (int off = 16; off > 0; off >>= 1)
                    h += __shfl_down_sync(0xffffffffu, h, off);
                if (lane == 0) red[q][w] = h;
            }
            __syncthreads();
            if (tid < cnt) {
                float s = red[tid][0] + red[tid][1] + red[tid][2] + red[tid][3]
                        + red[tid][4] + red[tid][5] + red[tid][6] + red[tid][7];
                float gate = sigmoidf_(s + b2);
                if (g == 0) gateL[j0 + tid] = gate;      // step gates stay local
                else        g_mg[b][j0 + tid] = gate;    // map gates -> global
            }
            __syncthreads();
        }
    }

    if (g == 1) {
        if (tid == 0) { __threadfence(); atomicAdd(&g_mgF[b * 16], 1u); }
    } else {
        const int nm = nJob[0], ns = nJob[1];

        // warp-collective sparse walk using LOCAL step gates (no wait!)
        if (w == 0) {
            #pragma unroll
            for (int i = lane; i < 40; i += 32) { wsI[i] = 0; wsW[i] = 0.f; }
            if (lane < Tn) { avI[lane] = 0; avW[lane] = 0.f; }

            int srcE = 0, tgtE = 0; float wE = 0.f;
            if (lane < ns) {
                int t = jobT[1][lane];
                srcE = e_src[t]; tgtE = e_ts[t]; wE = gateL[lane];
            }
            const int q = s_q; const float qv = s_qv;

            float c1 = (lane < ns && srcE == q) ? wE * qv : 0.f;
            float c2 = 0.f;
            for (int e = 0; e < ns; e++) {
                float ce = __shfl_sync(0xffffffffu, c1, e);
                int   te = __shfl_sync(0xffffffffu, tgtE, e);
                if (te == srcE) c2 += ce;
            }
            c2 *= wE;
            float c3 = 0.f;
            for (int e = 0; e < ns; e++) {
                float ce = __shfl_sync(0xffffffffu, c2, e);
                int   te = __shfl_sync(0xffffffffu, tgtE, e);
                if (te == srcE) c3 += ce;
            }
            c3 *= wE;
            float c123 = c1 + c2 + c3;

            // map-side accumulated walk mass (gates NOT needed yet)
            int mSrc = 0, mTgt = 0;
            if (lane < nm) {
                int t = jobT[0][lane];
                mSrc = e_src[t]; mTgt = e_tv[t];
            }
            float acc = (mSrc == q) ? qv : 0.f;
            for (int e = 0; e < ns; e++) {
                float ce = __shfl_sync(0xffffffffu, c123, e);
                int   te = __shfl_sync(0xffffffffu, tgtE, e);
                if (te == mSrc) acc += ce;
            }

            __syncwarp();
            if (lane == 0) { wsI[0] = q; wsW[0] = qv; }
            if (lane < ns) {
                wsI[1 + lane]          = tgtE; wsW[1 + lane]          = c1;
                wsI[1 + ns + lane]     = tgtE; wsW[1 + ns + lane]     = c2;
                wsI[1 + 2 * ns + lane] = tgtE; wsW[1 + 2 * ns + lane] = c3;
            }
            if (lane < nm) { avI[lane] = mTgt; avW[lane] = acc; }   // gate applied later
        }
        __syncthreads();

        // symbol gather overlaps the map-gate hop
        float ss = 0.f;
        #pragma unroll
        for (int p = 0; p < 37; p++)
            ss += wsW[p] * __ldg(&symbol_emb[wsI[p] * Dd + tid]);

        if (tid == 0)
            while ((int)(ldvol(&g_mgF[b * 16]) - Lt) < 0) { }
        __syncthreads();
        if (w == 0 && lane < nm) avW[lane] *= __ldcg(&g_mg[b][lane]);
        __syncthreads();

        float vv = 0.f;
        #pragma unroll
        for (int p = 0; p < Tn; p++)
            vv += avW[p] * __ldg(&value_emb[avI[p] * Dd + tid]);
        g_gs[b * (2 * Dd) + tid]      = ss;
        g_gs[b * (2 * Dd) + Dd + tid] = vv;
        __syncthreads();
        if (tid == 0) { __threadfence(); atomicAdd(&g_gsF[b * 16], 1u); }
    }

    // ======================= PHASE 2: hidden (full K=512) ====================
    // tile = bx: colt(4 x 64 cols) x rowt(16 x 4 rows) x z(2)
    {
        const int colt = bx & 3, rowt = (bx >> 2) & 15, z = bx >> 6;
        const float* W1 = z ? Wf1 : Wo1;
        const float* B1 = z ? bf1 : bo1;

        if (tid == 0) {
            const int b0 = rowt * 4;
            for (;;) {
                unsigned f0 = ldvol(&g_gsF[(b0 + 0) * 16]);
                unsigned f1 = ldvol(&g_gsF[(b0 + 1) * 16]);
                unsigned f2 = ldvol(&g_gsF[(b0 + 2) * 16]);
                unsigned f3 = ldvol(&g_gsF[(b0 + 3) * 16]);
                if ((int)(f0 - Lt) >= 0 && (int)(f1 - Lt) >= 0 &&
                    (int)(f2 - Lt) >= 0 && (int)(f3 - Lt) >= 0) break;
            }
        }
        __syncthreads();

        float* gs_s  = pool;           // [4][512]
        float* s_red = pool + 2048;    // [16][4][64]
        {
            const float4* src = (const float4*)&g_gs[rowt * 4 * 512];
            float4* dst = (float4*)gs_s;
            dst[tid]       = __ldcg(src + tid);
            dst[tid + 256] = __ldcg(src + tid + 256);
        }
        __syncthreads();

        const int cg = tid & 15, kq = tid >> 4;       // 16 col-groups x 16 k-chunks
        const int colg = colt * 64 + cg * 4;
        const float* Wp = W1 + (kq * 32) * Dd + colg;
        float4 a0 = {0,0,0,0}, a1 = {0,0,0,0}, a2 = {0,0,0,0}, a3 = {0,0,0,0};
        #pragma unroll
        for (int kk = 0; kk < 32; kk++) {
            float4 wv = *(const float4*)(Wp + kk * Dd);
            int k = kq * 32 + kk;
            float v0 = gs_s[k], v1 = gs_s[512 + k], v2 = gs_s[1024 + k], v3 = gs_s[1536 + k];
            a0.x += v0*wv.x; a0.y += v0*wv.y; a0.z += v0*wv.z; a0.w += v0*wv.w;
            a1.x += v1*wv.x; a1.y += v1*wv.y; a1.z += v1*wv.z; a1.w += v1*wv.w;
            a2.x += v2*wv.x; a2.y += v2*wv.y; a2.z += v2*wv.z; a2.w += v2*wv.w;
            a3.x += v3*wv.x; a3.y += v3*wv.y; a3.z += v3*wv.z; a3.w += v3*wv.w;
        }
        *(float4*)&s_red[(kq * 4 + 0) * 64 + cg * 4] = a0;
        *(float4*)&s_red[(kq * 4 + 1) * 64 + cg * 4] = a1;
        *(float4*)&s_red[(kq * 4 + 2) * 64 + cg * 4] = a2;
        *(float4*)&s_red[(kq * 4 + 3) * 64 + cg * 4] = a3;
        __syncthreads();

        {
            int r = tid >> 6, c = tid & 63;
            float s = 0.f;
            #pragma unroll
            for (int k2 = 0; k2 < 16; k2++) s += s_red[(k2 * 4 + r) * 64 + c];
            float hv = gelu_exact(s + B1[colt * 64 + c]);
            g_h[(z * Bsz + rowt * 4 + r) * Dd + colt * 64 + c] = hv;
        }
        __syncthreads();
        if (tid == 0) { __threadfence(); atomicAdd(&g_hF[(z * 16 + rowt) * 16], 1u); }
    }

    // ======================= PHASE 3: output (full K=256, direct store) ======
    if (bx < 96) {
        int z, rowt, colt;
        if (bx < 64) { z = 0; rowt = bx >> 2;        colt = bx & 3; }
        else         { z = 1; rowt = (bx - 64) >> 1; colt = (bx - 64) & 1; }
        const int OW = z ? Dd : Vv;
        const float* W2 = z ? Wf2 : Wo2;
        const float* B2 = z ? bf2 : bo2;

        if (tid == 0) {
            const unsigned tgt = 4u * Lt;
            while ((int)(ldvol(&g_hF[(z * 16 + rowt) * 16]) - tgt) < 0) { }
        }
        __syncthreads();

        float* h_s   = pool;          // [4][256]
        float* s_red = pool + 1024;   // [8][4][128]
        ((float4*)h_s)[tid] = __ldcg((const float4*)&g_h[(z * Bsz + rowt * 4) * Dd] + tid);
        __syncthreads();

        const int cg = tid & 31, kq = tid >> 5;      // 32 col-groups x 8 k-chunks
        const int colg = colt * 128 + cg * 4;
        const float* Wp = W2 + (kq * 32) * OW + colg;
        float4 a0 = {0,0,0,0}, a1 = {0,0,0,0}, a2 = {0,0,0,0}, a3 = {0,0,0,0};
        #pragma unroll
        for (int kk = 0; kk < 32; kk++) {
            float4 wv = *(const float4*)(Wp + kk * OW);
            int k = kq * 32 + kk;
            float v0 = h_s[k], v1 = h_s[256 + k], v2 = h_s[512 + k], v3 = h_s[768 + k];
            a0.x += v0*wv.x; a0.y += v0*wv.y; a0.z += v0*wv.z; a0.w += v0*wv.w;
            a1.x += v1*wv.x; a1.y += v1*wv.y; a1.z += v1*wv.z; a1.w += v1*wv.w;
            a2.x += v2*wv.x; a2.y += v2*wv.y; a2.z += v2*wv.z; a2.w += v2*wv.w;
            a3.x += v3*wv.x; a3.y += v3*wv.y; a3.z += v3*wv.z; a3.w += v3*wv.w;
        }
        *(float4*)&s_red[(kq * 4 + 0) * 128 + cg * 4] = a0;
        *(float4*)&s_red[(kq * 4 + 1) * 128 + cg * 4] = a1;
        *(float4*)&s_red[(kq * 4 + 2) * 128 + cg * 4] = a2;
        *(float4*)&s_red[(kq * 4 + 3) * 128 + cg * 4] = a3;
        __syncthreads();

        float* ob = z ? (out + Bsz * Vv) : out;
        #pragma unroll
        for (int u = 0; u < 2; u++) {
            int idx = tid + u * 256;
            int r = idx >> 7, c = idx & 127;
            float s = 0.f;
            #pragma unroll
            for (int k2 = 0; k2 < 8; k2++) s += s_red[(k2 * 4 + r) * 128 + c];
            ob[(rowt * 4 + r) * OW + colt * 128 + c] = s + B2[colt * 128 + c];
        }
    }
}

// ---------------------------------------------------------------------------
extern "C" void kernel_launch(void* const* d_in, const int* in_sizes, int n_in,
                              void* d_out, int out_size)
{
    const int*   marker     = (const int*)d_in[0];
    const int*   srcI       = (const int*)d_in[1];
    const int*   sv         = (const int*)d_in[2];
    const int*   tsymI      = (const int*)d_in[3];
    const int*   tsv        = (const int*)d_in[4];
    const int*   tvalI      = (const int*)d_in[5];
    const int*   tvv        = (const int*)d_in[6];
    const int*   qI         = (const int*)d_in[7];
    const int*   qV         = (const int*)d_in[8];
    const float* evidence   = (const float*)d_in[9];
    const float* symbol_emb = (const float*)d_in[10];
    const float* value_emb  = (const float*)d_in[11];
    const float* Wmg1 = (const float*)d_in[12]; const float* bmg1 = (const float*)d_in[13];
    const float* Wmg2 = (const float*)d_in[14]; const float* bmg2 = (const float*)d_in[15];
    const float* Wsg1 = (const float*)d_in[16]; const float* bsg1 = (const float*)d_in[17];
    const float* Wsg2 = (const float*)d_in[18]; const float* bsg2 = (const float*)d_in[19];
    const float* Wf1  = (const float*)d_in[20]; const float* bf1  = (const float*)d_in[21];
    const float* Wf2  = (const float*)d_in[22]; const float* bf2  = (const float*)d_in[23];
    const float* Wo1  = (const float*)d_in[24]; const float* bo1  = (const float*)d_in[25];
    const float* Wo2  = (const float*)d_in[26]; const float* bo2  = (const float*)d_in[27];
    float* out = (float*)d_out;

    k_all<<<NB, 256>>>(marker, srcI, sv, tsymI, tsv, tvalI, tvv, qI, qV,
                       evidence, symbol_emb, value_emb,
                       Wmg1, bmg1, Wmg2, bmg2, Wsg1, bsg1, Wsg2, bsg2,
                       Wf1, bf1, Wf2, bf2, Wo1, bo1, Wo2, bo2, out);
}

// round 12
// speedup vs baseline: 1.4083x; 1.1003x over previous
#include <cuda_runtime.h>
#include <math.h>

#define Bsz 64
#define Tn  12
#define Dd  256
#define Vv  512
#define Ss  512
#define NB  128   // all CTAs co-resident in one wave (128 <= 148 SMs)

// ---- persistent scratch (no allocations allowed) ----
__device__ unsigned g_ep[NB * 16];                // per-block launch counters (64B stride)
__device__ unsigned g_gsF[Bsz * 16];              // gs ready flags   (64B stride)
__device__ unsigned g_mgF[Bsz * 16];              // map-gate flags   (64B stride)
__device__ unsigned g_hF[32 * 16];                // h tile flags [z*16+rowt]
__device__ float    g_gs[Bsz * 2 * Dd];           // graph_state [64][512]
__device__ float    g_mg[Bsz][Tn];                // map gates (producer->walker)
__device__ __align__(16) float g_h[2 * Bsz * Dd]; // gelu'd hidden [z][64][256]

__device__ __forceinline__ float gelu_exact(float x) {
    return 0.5f * x * (1.0f + erff(x * 0.70710678118654752440f));
}
__device__ __forceinline__ float sigmoidf_(float x) {
    return 1.0f / (1.0f + expf(-x));
}
__device__ __forceinline__ unsigned ldvol(const unsigned* p) {
    return *(volatile const unsigned*)p;
}
// release-increment of a flag (no separate membar needed)
__device__ __forceinline__ void rel_add(unsigned* p) {
    asm volatile("red.release.gpu.global.add.u32 [%0], 1;" :: "l"(p) : "memory");
}
// acquire-load of a flag
__device__ __forceinline__ unsigned acq_ld(const unsigned* p) {
    unsigned v;
    asm volatile("ld.acquire.gpu.global.u32 %0, [%1];" : "=r"(v) : "l"(p) : "memory");
    return v;
}

// ---------------------------------------------------------------------------
__global__ void __launch_bounds__(256)
k_all(const int* __restrict__ marker, const int* __restrict__ srcI,
      const int* __restrict__ sv,
      const int* __restrict__ tsymI, const int* __restrict__ tsv,
      const int* __restrict__ tvalI, const int* __restrict__ tvv,
      const int* __restrict__ qI, const int* __restrict__ qV,
      const float* __restrict__ evidence,
      const float* __restrict__ symbol_emb, const float* __restrict__ value_emb,
      const float* __restrict__ Wmg1, const float* __restrict__ bmg1,
      const float* __restrict__ Wmg2, const float* __restrict__ bmg2,
      const float* __restrict__ Wsg1, const float* __restrict__ bsg1,
      const float* __restrict__ Wsg2, const float* __restrict__ bsg2,
      const float* __restrict__ Wf1,  const float* __restrict__ bf1,
      const float* __restrict__ Wf2,  const float* __restrict__ bf2,
      const float* __restrict__ Wo1,  const float* __restrict__ bo1,
      const float* __restrict__ Wo2,  const float* __restrict__ bo2,
      float* __restrict__ out)
{
    const int bx  = blockIdx.x;
    const int tid = threadIdx.x;
    const int lane = tid & 31, w = tid >> 5;

    __shared__ __align__(16) float pool[7168];     // 28KB, reused per phase
    __shared__ int   e_m[Tn], e_src[Tn], e_sv[Tn], e_ts[Tn], e_tsv[Tn], e_tv[Tn], e_tvv[Tn];
    __shared__ int   jobT[2][Tn];
    __shared__ int   nJob[2];
    __shared__ float gateL[Tn];                    // locally computed gates
    __shared__ float red[4][8];
    __shared__ int   wsI[40]; __shared__ float wsW[40];   // 1+3*12 = 37 used
    __shared__ int   avI[Tn]; __shared__ float avW[Tn];
    __shared__ unsigned s_L;
    __shared__ int   s_q; __shared__ float s_qv;

    // per-block private launch counter: zero contention, graph-replay safe
    if (tid == 0) {
        unsigned v = ldvol(&g_ep[bx * 16]);
        *(volatile unsigned*)&g_ep[bx * 16] = v + 1u;
        s_L = v;
    }

    // ======================= PHASE 1 =========================================
    // g=0: step gates (local) + walk + gather.  g=1: map gates -> global.
    const int b = bx & (Bsz - 1);
    const int g = bx >> 6;
    const int gt = 1 - g;                  // gate type computed here: 0=map, 1=step

    // parallel event load: 84 threads, one LDG each
    if (tid < 84) {
        const int a = tid / 12, t = tid - a * 12;
        const int idx = b * Tn + t;
        int v;
        switch (a) {
            case 0: e_m[t]   = marker[idx]; break;
            case 1: v = srcI[idx];  e_src[t] = min(max(v, 0), Ss - 1); break;
            case 2: e_sv[t]  = sv[idx]; break;
            case 3: v = tsymI[idx]; e_ts[t]  = min(max(v, 0), Ss - 1); break;
            case 4: e_tsv[t] = tsv[idx]; break;
            case 5: v = tvalI[idx]; e_tv[t]  = min(max(v, 0), Vv - 1); break;
            case 6: e_tvv[t] = tvv[idx]; break;
        }
    } else if (tid == 84) {
        s_q = min(max(qI[b], 0), Ss - 1); s_qv = (float)qV[b];
    }
    __syncthreads();

    if (w == 0) {
        int fm = 0, fs = 0;
        if (lane < Tn) {
            int m = e_m[lane];
            fm = (((m == 0) || (m == 1)) && e_sv[lane] > 0 && e_tvv[lane] > 0) ? 1 : 0;
            fs = ((m == 2) && e_sv[lane] > 0 && e_tsv[lane] > 0) ? 1 : 0;
        }
        unsigned bm = __ballot_sync(0xffffffffu, fm);
        unsigned bs = __ballot_sync(0xffffffffu, fs);
        if (fm) jobT[0][__popc(bm & ((1u << lane) - 1u))] = lane;
        if (fs) jobT[1][__popc(bs & ((1u << lane) - 1u))] = lane;
        if (lane == 0) { nJob[0] = __popc(bm); nJob[1] = __popc(bs); }
    }
    __syncthreads();

    const unsigned Lt = s_L + 1u;
    const int nj = nJob[gt];

    // stage active jobs' evidence rows
    float* s_ev   = pool;                  // [<=12][256]
    float* s_part = pool + Tn * Dd;        // [4][4][256]
    for (int jj = 0; jj < nj; jj++)
        s_ev[jj * Dd + tid] = evidence[(b * Tn + jobT[gt][jj]) * Dd + tid];
    __syncthreads();

    // gate MLP passes for this block's gate type
    {
        const float* W1 = gt ? Wsg1 : Wmg1;
        const float* B1 = gt ? bsg1 : bmg1;
        const float* W2 = gt ? Wsg2 : Wmg2;
        const float  b2 = gt ? bsg2[0] : bmg2[0];
        const int cg = w & 1, kq = w >> 1;
        const int colb = cg * 128 + lane * 4;

        for (int j0 = 0; j0 < nj; j0 += 4) {
            int cnt = nj - j0; if (cnt > 4) cnt = 4;
            const float* Wp = W1 + (kq * 64) * Dd + colb;
            const float* x0 = s_ev + (j0) * Dd;
            const float* x1 = s_ev + (j0 + (cnt > 1 ? 1 : 0)) * Dd;

            if (cnt <= 2) {
                float4 a0 = {0,0,0,0}, a1 = {0,0,0,0};
                #pragma unroll 16
                for (int kk = 0; kk < 64; kk++) {
                    float4 wv = *(const float4*)(Wp + kk * Dd);
                    int k = kq * 64 + kk;
                    float v0 = x0[k], v1 = x1[k];
                    a0.x += v0*wv.x; a0.y += v0*wv.y; a0.z += v0*wv.z; a0.w += v0*wv.w;
                    a1.x += v1*wv.x; a1.y += v1*wv.y; a1.z += v1*wv.z; a1.w += v1*wv.w;
                }
                *(float4*)&s_part[(kq * 4 + 0) * Dd + colb] = a0;
                *(float4*)&s_part[(kq * 4 + 1) * Dd + colb] = a1;
            } else {
                const float* x2 = s_ev + (j0 + 2) * Dd;
                const float* x3 = s_ev + (j0 + (cnt > 3 ? 3 : 2)) * Dd;
                float4 a0 = {0,0,0,0}, a1 = {0,0,0,0}, a2 = {0,0,0,0}, a3 = {0,0,0,0};
                #pragma unroll 16
                for (int kk = 0; kk < 64; kk++) {
                    float4 wv = *(const float4*)(Wp + kk * Dd);
                    int k = kq * 64 + kk;
                    float v0 = x0[k], v1 = x1[k], v2 = x2[k], v3 = x3[k];
                    a0.x += v0*wv.x; a0.y += v0*wv.y; a0.z += v0*wv.z; a0.w += v0*wv.w;
                    a1.x += v1*wv.x; a1.y += v1*wv.y; a1.z += v1*wv.z; a1.w += v1*wv.w;
                    a2.x += v2*wv.x; a2.y += v2*wv.y; a2.z += v2*wv.z; a2.w += v2*wv.w;
                    a3.x += v3*wv.x; a3.y += v3*wv.y; a3.z += v3*wv.z; a3.w += v3*wv.w;
                }
                *(float4*)&s_part[(kq * 4 + 0) * Dd + colb] = a0;
                *(float4*)&s_part[(kq * 4 + 1) * Dd + colb] = a1;
                *(float4*)&s_part[(kq * 4 + 2) * Dd + colb] = a2;
                *(float4*)&s_part[(kq * 4 + 3) * Dd + colb] = a3;
            }
            __syncthreads();

            float b1v = B1[tid], w2v = W2[tid];
            for (int q = 0; q < cnt; q++) {
                float h = gelu_exact(s_part[(0 * 4 + q) * Dd + tid] + s_part[(1 * 4 + q) * Dd + tid]
                                   + s_part[(2 * 4 + q) * Dd + tid] + s_part[(3 * 4 + q) * Dd + tid]
                                   + b1v) * w2v;
                #pragma unroll
                for (int off = 16; off > 0; off >>= 1)
                    h += __shfl_down_sync(0xffffffffu, h, off);
                if (lane == 0) red[q][w] = h;
            }
            __syncthreads();
            if (tid < cnt) {
                float s = red[tid][0] + red[tid][1] + red[tid][2] + red[tid][3]
                        + red[tid][4] + red[tid][5] + red[tid][6] + red[tid][7];
                float gate = sigmoidf_(s + b2);
                if (g == 0) gateL[j0 + tid] = gate;      // step gates stay local
                else        g_mg[b][j0 + tid] = gate;    // map gates -> global
            }
            __syncthreads();
        }
    }

    if (g == 1) {
        if (tid == 0) rel_add(&g_mgF[b * 16]);
    } else {
        const int nm = nJob[0], ns = nJob[1];

        // warp-collective sparse walk using LOCAL step gates (no wait!)
        if (w == 0) {
            #pragma unroll
            for (int i = lane; i < 40; i += 32) { wsI[i] = 0; wsW[i] = 0.f; }
            if (lane < Tn) { avI[lane] = 0; avW[lane] = 0.f; }

            int srcE = 0, tgtE = 0; float wE = 0.f;
            if (lane < ns) {
                int t = jobT[1][lane];
                srcE = e_src[t]; tgtE = e_ts[t]; wE = gateL[lane];
            }
            const int q = s_q; const float qv = s_qv;

            float c1 = (lane < ns && srcE == q) ? wE * qv : 0.f;
            float c2 = 0.f;
            for (int e = 0; e < ns; e++) {
                float ce = __shfl_sync(0xffffffffu, c1, e);
                int   te = __shfl_sync(0xffffffffu, tgtE, e);
                if (te == srcE) c2 += ce;
            }
            c2 *= wE;
            float c3 = 0.f;
            for (int e = 0; e < ns; e++) {
                float ce = __shfl_sync(0xffffffffu, c2, e);
                int   te = __shfl_sync(0xffffffffu, tgtE, e);
                if (te == srcE) c3 += ce;
            }
            c3 *= wE;
            float c123 = c1 + c2 + c3;

            int mSrc = 0, mTgt = 0;
            if (lane < nm) {
                int t = jobT[0][lane];
                mSrc = e_src[t]; mTgt = e_tv[t];
            }
            float acc = (mSrc == q) ? qv : 0.f;
            for (int e = 0; e < ns; e++) {
                float ce = __shfl_sync(0xffffffffu, c123, e);
                int   te = __shfl_sync(0xffffffffu, tgtE, e);
                if (te == mSrc) acc += ce;
            }

            __syncwarp();
            if (lane == 0) { wsI[0] = q; wsW[0] = qv; }
            if (lane < ns) {
                wsI[1 + lane]          = tgtE; wsW[1 + lane]          = c1;
                wsI[1 + ns + lane]     = tgtE; wsW[1 + ns + lane]     = c2;
                wsI[1 + 2 * ns + lane] = tgtE; wsW[1 + 2 * ns + lane] = c3;
            }
            if (lane < nm) { avI[lane] = mTgt; avW[lane] = acc; }   // gate applied later
        }
        __syncthreads();

        // symbol gather overlaps the map-gate hop
        float ss = 0.f;
        #pragma unroll
        for (int p = 0; p < 37; p++)
            ss += wsW[p] * __ldg(&symbol_emb[wsI[p] * Dd + tid]);

        if (tid == 0)
            while ((int)(acq_ld(&g_mgF[b * 16]) - Lt) < 0) { }
        __syncthreads();
        if (w == 0 && lane < nm) avW[lane] *= __ldcg(&g_mg[b][lane]);
        __syncthreads();

        float vv = 0.f;
        #pragma unroll
        for (int p = 0; p < Tn; p++)
            vv += avW[p] * __ldg(&value_emb[avI[p] * Dd + tid]);
        g_gs[b * (2 * Dd) + tid]      = ss;
        g_gs[b * (2 * Dd) + Dd + tid] = vv;
        __syncthreads();
        if (tid == 0) rel_add(&g_gsF[b * 16]);
    }

    // ======================= PHASE 2: hidden (full K=512) ====================
    // tile = bx: colt(4 x 64 cols) x rowt(16 x 4 rows) x z(2)
    {
        const int colt = bx & 3, rowt = (bx >> 2) & 15, z = bx >> 6;
        const float* W1 = z ? Wf1 : Wo1;
        const float* B1 = z ? bf1 : bo1;
        const int cg = tid & 15, kq = tid >> 4;       // 16 col-groups x 16 k-chunks
        const int colg = colt * 64 + cg * 4;
        const float* Wp = W1 + (kq * 32) * Dd + colg;

        // prefetch first half of W slice BEFORE the flag wait (indep of gs)
        float4 w0[16];
        #pragma unroll
        for (int i = 0; i < 16; i++) w0[i] = *(const float4*)(Wp + i * Dd);

        if (tid == 0) {
            const int b0 = rowt * 4;
            for (;;) {
                unsigned f0 = acq_ld(&g_gsF[(b0 + 0) * 16]);
                unsigned f1 = acq_ld(&g_gsF[(b0 + 1) * 16]);
                unsigned f2 = acq_ld(&g_gsF[(b0 + 2) * 16]);
                unsigned f3 = acq_ld(&g_gsF[(b0 + 3) * 16]);
                if ((int)(f0 - Lt) >= 0 && (int)(f1 - Lt) >= 0 &&
                    (int)(f2 - Lt) >= 0 && (int)(f3 - Lt) >= 0) break;
            }
        }
        __syncthreads();

        float* gs_s  = pool;           // [4][512]
        float* s_red = pool + 2048;    // [16][4][64]
        {
            const float4* src = (const float4*)&g_gs[rowt * 4 * 512];
            float4* dst = (float4*)gs_s;
            dst[tid]       = __ldcg(src + tid);
            dst[tid + 256] = __ldcg(src + tid + 256);
        }
        __syncthreads();

        // second half of W slice: issues while first-half FFMAs run
        float4 w1[16];
        #pragma unroll
        for (int i = 0; i < 16; i++) w1[i] = *(const float4*)(Wp + (16 + i) * Dd);

        float4 a0 = {0,0,0,0}, a1 = {0,0,0,0}, a2 = {0,0,0,0}, a3 = {0,0,0,0};
        #pragma unroll
        for (int kk = 0; kk < 16; kk++) {
            float4 wv = w0[kk];
            int k = kq * 32 + kk;
            float v0 = gs_s[k], v1 = gs_s[512 + k], v2 = gs_s[1024 + k], v3 = gs_s[1536 + k];
            a0.x += v0*wv.x; a0.y += v0*wv.y; a0.z += v0*wv.z; a0.w += v0*wv.w;
            a1.x += v1*wv.x; a1.y += v1*wv.y; a1.z += v1*wv.z; a1.w += v1*wv.w;
            a2.x += v2*wv.x; a2.y += v2*wv.y; a2.z += v2*wv.z; a2.w += v2*wv.w;
            a3.x += v3*wv.x; a3.y += v3*wv.y; a3.z += v3*wv.z; a3.w += v3*wv.w;
        }
        #pragma unroll
        for (int kk = 0; kk < 16; kk++) {
            float4 wv = w1[kk];
            int k = kq * 32 + 16 + kk;
            float v0 = gs_s[k], v1 = gs_s[512 + k], v2 = gs_s[1024 + k], v3 = gs_s[1536 + k];
            a0.x += v0*wv.x; a0.y += v0*wv.y; a0.z += v0*wv.z; a0.w += v0*wv.w;
            a1.x += v1*wv.x; a1.y += v1*wv.y; a1.z += v1*wv.z; a1.w += v1*wv.w;
            a2.x += v2*wv.x; a2.y += v2*wv.y; a2.z += v2*wv.z; a2.w += v2*wv.w;
            a3.x += v3*wv.x; a3.y += v3*wv.y; a3.z += v3*wv.z; a3.w += v3*wv.w;
        }
        *(float4*)&s_red[(kq * 4 + 0) * 64 + cg * 4] = a0;
        *(float4*)&s_red[(kq * 4 + 1) * 64 + cg * 4] = a1;
        *(float4*)&s_red[(kq * 4 + 2) * 64 + cg * 4] = a2;
        *(float4*)&s_red[(kq * 4 + 3) * 64 + cg * 4] = a3;
        __syncthreads();

        {
            int r = tid >> 6, c = tid & 63;
            float s = 0.f;
            #pragma unroll
            for (int k2 = 0; k2 < 16; k2++) s += s_red[(k2 * 4 + r) * 64 + c];
            float hv = gelu_exact(s + B1[colt * 64 + c]);
            g_h[(z * Bsz + rowt * 4 + r) * Dd + colt * 64 + c] = hv;
        }
        __syncthreads();
        if (tid == 0) rel_add(&g_hF[(z * 16 + rowt) * 16]);
    }

    // ======================= PHASE 3: output (full K=256, direct store) ======
    if (bx < 96) {
        int z, rowt, colt;
        if (bx < 64) { z = 0; rowt = bx >> 2;        colt = bx & 3; }
        else         { z = 1; rowt = (bx - 64) >> 1; colt = (bx - 64) & 1; }
        const int OW = z ? Dd : Vv;
        const float* W2 = z ? Wf2 : Wo2;
        const float* B2 = z ? bf2 : bo2;
        const int cg = tid & 31, kq = tid >> 5;      // 32 col-groups x 8 k-chunks
        const int colg = colt * 128 + cg * 4;
        const float* Wp = W2 + (kq * 32) * OW + colg;

        // prefetch first half of W2 slice before the h wait
        float4 w0[16];
        #pragma unroll
        for (int i = 0; i < 16; i++) w0[i] = *(const float4*)(Wp + i * OW);

        if (tid == 0) {
            const unsigned tgt = 4u * Lt;
            while ((int)(acq_ld(&g_hF[(z * 16 + rowt) * 16]) - tgt) < 0) { }
        }
        __syncthreads();

        float* h_s   = pool;          // [4][256]
        float* s_red = pool + 1024;   // [8][4][128]
        ((float4*)h_s)[tid] = __ldcg((const float4*)&g_h[(z * Bsz + rowt * 4) * Dd] + tid);
        __syncthreads();

        float4 w1[16];
        #pragma unroll
        for (int i = 0; i < 16; i++) w1[i] = *(const float4*)(Wp + (16 + i) * OW);

        float4 a0 = {0,0,0,0}, a1 = {0,0,0,0}, a2 = {0,0,0,0}, a3 = {0,0,0,0};
        #pragma unroll
        for (int kk = 0; kk < 16; kk++) {
            float4 wv = w0[kk];
            int k = kq * 32 + kk;
            float v0 = h_s[k], v1 = h_s[256 + k], v2 = h_s[512 + k], v3 = h_s[768 + k];
            a0.x += v0*wv.x; a0.y += v0*wv.y; a0.z += v0*wv.z; a0.w += v0*wv.w;
            a1.x += v1*wv.x; a1.y += v1*wv.y; a1.z += v1*wv.z; a1.w += v1*wv.w;
            a2.x += v2*wv.x; a2.y += v2*wv.y; a2.z += v2*wv.z; a2.w += v2*wv.w;
            a3.x += v3*wv.x; a3.y += v3*wv.y; a3.z += v3*wv.z; a3.w += v3*wv.w;
        }
        #pragma unroll
        for (int kk = 0; kk < 16; kk++) {
            float4 wv = w1[kk];
            int k = kq * 32 + 16 + kk;
            float v0 = h_s[k], v1 = h_s[256 + k], v2 = h_s[512 + k], v3 = h_s[768 + k];
            a0.x += v0*wv.x; a0.y += v0*wv.y; a0.z += v0*wv.z; a0.w += v0*wv.w;
            a1.x += v1*wv.x; a1.y += v1*wv.y; a1.z += v1*wv.z; a1.w += v1*wv.w;
            a2.x += v2*wv.x; a2.y += v2*wv.y; a2.z += v2*wv.z; a2.w += v2*wv.w;
            a3.x += v3*wv.x; a3.y += v3*wv.y; a3.z += v3*wv.z; a3.w += v3*wv.w;
        }
        *(float4*)&s_red[(kq * 4 + 0) * 128 + cg * 4] = a0;
        *(float4*)&s_red[(kq * 4 + 1) * 128 + cg * 4] = a1;
        *(float4*)&s_red[(kq * 4 + 2) * 128 + cg * 4] = a2;
        *(float4*)&s_red[(kq * 4 + 3) * 128 + cg * 4] = a3;
        __syncthreads();

        float* ob = z ? (out + Bsz * Vv) : out;
        #pragma unroll
        for (int u = 0; u < 2; u++) {
            int idx = tid + u * 256;
            int r = idx >> 7, c = idx & 127;
            float s = 0.f;
            #pragma unroll
            for (int k2 = 0; k2 < 8; k2++) s += s_red[(k2 * 4 + r) * 128 + c];
            ob[(rowt * 4 + r) * OW + colt * 128 + c] = s + B2[colt * 128 + c];
        }
    }
}

// ---------------------------------------------------------------------------
extern "C" void kernel_launch(void* const* d_in, const int* in_sizes, int n_in,
                              void* d_out, int out_size)
{
    const int*   marker     = (const int*)d_in[0];
    const int*   srcI       = (const int*)d_in[1];
    const int*   sv         = (const int*)d_in[2];
    const int*   tsymI      = (const int*)d_in[3];
    const int*   tsv        = (const int*)d_in[4];
    const int*   tvalI      = (const int*)d_in[5];
    const int*   tvv        = (const int*)d_in[6];
    const int*   qI         = (const int*)d_in[7];
    const int*   qV         = (const int*)d_in[8];
    const float* evidence   = (const float*)d_in[9];
    const float* symbol_emb = (const float*)d_in[10];
    const float* value_emb  = (const float*)d_in[11];
    const float* Wmg1 = (const float*)d_in[12]; const float* bmg1 = (const float*)d_in[13];
    const float* Wmg2 = (const float*)d_in[14]; const float* bmg2 = (const float*)d_in[15];
    const float* Wsg1 = (const float*)d_in[16]; const float* bsg1 = (const float*)d_in[17];
    const float* Wsg2 = (const float*)d_in[18]; const float* bsg2 = (const float*)d_in[19];
    const float* Wf1  = (const float*)d_in[20]; const float* bf1  = (const float*)d_in[21];
    const float* Wf2  = (const float*)d_in[22]; const float* bf2  = (const float*)d_in[23];
    const float* Wo1  = (const float*)d_in[24]; const float* bo1  = (const float*)d_in[25];
    const float* Wo2  = (const float*)d_in[26]; const float* bo2  = (const float*)d_in[27];
    float* out = (float*)d_out;

    k_all<<<NB, 256>>>(marker, srcI, sv, tsymI, tsv, tvalI, tvv, qI, qV,
                       evidence, symbol_emb, value_emb,
                       Wmg1, bmg1, Wmg2, bmg2, Wsg1, bsg1, Wsg2, bsg2,
                       Wf1, bf1, Wf2, bf2, Wo1, bo1, Wo2, bo2, out);
}